// round 9
// baseline (speedup 1.0000x reference)
#include <cuda_runtime.h>
#include <cuda_fp16.h>

#define N_NODES 10000
#define N_EDGES 640000
#define D_FEAT  128

// ---------------- scratch (static device globals; no allocations) ----------------
__device__ __align__(256) float  g_dinv[N_NODES];
__device__ __align__(256) int    g_count[N_NODES];
__device__ __align__(256) int    g_cur[N_NODES];
__device__ __align__(256) int    g_off[N_NODES + 1];
__device__ __align__(256) int    g_csr_src[N_EDGES];       // src only; weight on the fly
__device__ __align__(256) float  g_bufA[N_NODES * D_FEAT]; // agg output (fp32, GEMM A)
__device__ __align__(256) __half g_bufH[N_NODES * D_FEAT]; // fp16 features (agg input)
__device__ int g_is64;

// ---------------- packed f32x2 helpers (sm_100a) ----------------
__device__ __forceinline__ unsigned long long pack2(float x, float y) {
    unsigned long long r;
    asm("mov.b64 %0, {%1, %2};" : "=l"(r) : "f"(x), "f"(y));
    return r;
}
__device__ __forceinline__ void unpack2(unsigned long long v, float& x, float& y) {
    asm("mov.b64 {%0, %1}, %2;" : "=f"(x), "=f"(y) : "l"(v));
}
__device__ __forceinline__ void ffma2(unsigned long long& c,
                                      unsigned long long a, unsigned long long b) {
    asm("fma.rn.f32x2 %0, %1, %2, %0;" : "+l"(c) : "l"(a), "l"(b));
}

// ---------------- structure kernels ----------------

// zero counters + dtype-detect (warp 0 of block 0).
__global__ void k_init(const int* __restrict__ ei32) {
    int t = threadIdx.x;
    int i = blockIdx.x * blockDim.x + t;
    if (i < N_NODES) { g_count[i] = 0; g_cur[i] = 0; }
    if (blockIdx.x == 0 && t < 32) {
        int any = 0;
#pragma unroll 8
        for (int k = 0; k < 32; k++) any |= ei32[2 * (t * 32 + k) + 1];
        int is64 = __any_sync(0xffffffffu, any != 0) ? 0 : 1;
        if (t == 0) g_is64 = is64;
    }
}

__device__ __forceinline__ void load4(const void* ei, int base4, int row, int* v) {
    if (g_is64) {
        const longlong2* p = (const longlong2*)ei + row * (N_EDGES / 2) + base4 * 2;
        longlong2 a = p[0], b = p[1];
        v[0] = (int)a.x; v[1] = (int)a.y; v[2] = (int)b.x; v[3] = (int)b.y;
    } else {
        int4 a = ((const int4*)ei)[row * (N_EDGES / 4) + base4];
        v[0] = a.x; v[1] = a.y; v[2] = a.z; v[3] = a.w;
    }
}

#define HIST_BLOCKS ((N_EDGES / 4 + 255) / 256)          // 625
#define CVT_BLOCKS  ((N_NODES * D_FEAT / 4 + 255) / 256) // 1250

// fused: histogram of dst row (4 edges/thread) + fp32->fp16 convert of x
__global__ void k_histcvt(const void* __restrict__ ei, const float* __restrict__ x) {
    if (blockIdx.x < HIST_BLOCKS) {
        int i = blockIdx.x * blockDim.x + threadIdx.x;
        if (i < N_EDGES / 4) {
            int d[4];
            load4(ei, i, 1, d);
#pragma unroll
            for (int q = 0; q < 4; q++)
                if ((unsigned)d[q] < N_NODES) atomicAdd(&g_count[d[q]], 1);
        }
    } else {
        int i = (blockIdx.x - HIST_BLOCKS) * blockDim.x + threadIdx.x;
        if (i < N_NODES * D_FEAT / 4) {
            float4 v = ((const float4*)x)[i];
            __half2 h0 = __floats2half2_rn(v.x, v.y);
            __half2 h1 = __floats2half2_rn(v.z, v.w);
            uint2 u;
            u.x = *(unsigned*)&h0;
            u.y = *(unsigned*)&h1;
            ((uint2*)g_bufH)[i] = u;
        }
    }
}

// single-block exclusive scan of g_count -> g_off, plus dinv
__global__ void k_scan() {
    __shared__ int part[1024];
    const int CH = 10;
    int t = threadIdx.x;
    int base = t * CH;
    int s = 0;
#pragma unroll
    for (int i = 0; i < CH; i++) {
        int idx = base + i;
        if (idx < N_NODES) s += g_count[idx];
    }
    part[t] = s;
    __syncthreads();
    for (int d = 1; d < 1024; d <<= 1) {
        int v = (t >= d) ? part[t - d] : 0;
        __syncthreads();
        part[t] += v;
        __syncthreads();
    }
    int run = (t == 0) ? 0 : part[t - 1];
#pragma unroll
    for (int i = 0; i < CH; i++) {
        int idx = base + i;
        if (idx < N_NODES) {
            int c = g_count[idx];
            g_off[idx] = run;
            run += c;
            g_dinv[idx] = rsqrtf((float)(c + 1));   // +1 self-loop
        } else if (idx == N_NODES) {
            g_off[N_NODES] = run;
        }
    }
}

// CSR fill (src only), 4 edges per thread
__global__ void k_scatter(const void* __restrict__ ei) {
    int i = blockIdx.x * blockDim.x + threadIdx.x;
    if (i < N_EDGES / 4) {
        int s[4], d[4];
        load4(ei, i, 0, s);
        load4(ei, i, 1, d);
#pragma unroll
        for (int q = 0; q < 4; q++) {
            if ((unsigned)d[q] < N_NODES) {
                int p = g_off[d[q]] + atomicAdd(&g_cur[d[q]], 1);
                int sv = ((unsigned)s[q] < N_NODES) ? s[q] : 0;
                g_csr_src[p] = sv;
            }
        }
    }
}

// ---------------- aggregation: one warp per destination node ----------------
// out[v] = dinv[v]^2 * in[v] + sum_e dinv[s]*dinv[v] * in[s]
// CSR loads lane-split (lanes 0..7) + shfl broadcast; weight on the fly.
__global__ void __launch_bounds__(256) k_agg() {
    const __half* __restrict__ fin = g_bufH;
    float* __restrict__ fout = g_bufA;

    int v    = (blockIdx.x * blockDim.x + threadIdx.x) >> 5;
    int lane = threadIdx.x & 31;
    if (v >= N_NODES) return;

    float dv = g_dinv[v];
    float sl = dv * dv;

    uint2 ux = ((const uint2*)(fin + (size_t)v * D_FEAT))[lane];
    float2 x0 = __half22float2(*(__half2*)&ux.x);
    float2 x1 = __half22float2(*(__half2*)&ux.y);
    float4 acc = make_float4(x0.x * sl, x0.y * sl, x1.x * sl, x1.y * sl);

    int j   = g_off[v];
    int end = g_off[v + 1];
    for (; j + 8 <= end; j += 8) {
        int eL = 0; float dsL = 0.f;
        if (lane < 8) {
            eL  = g_csr_src[j + lane];
            dsL = g_dinv[eL];
        }
        int   s[8];
        float w[8];
#pragma unroll
        for (int q = 0; q < 8; q++) {
            s[q] = __shfl_sync(0xffffffffu, eL, q);
            w[q] = __shfl_sync(0xffffffffu, dsL, q) * dv;
        }
        uint2 u[8];
#pragma unroll
        for (int q = 0; q < 8; q++)
            u[q] = ((const uint2*)(fin + (size_t)s[q] * D_FEAT))[lane];
#pragma unroll
        for (int q = 0; q < 8; q++) {
            float2 f0 = __half22float2(*(__half2*)&u[q].x);
            float2 f1 = __half22float2(*(__half2*)&u[q].y);
            acc.x += w[q] * f0.x; acc.y += w[q] * f0.y;
            acc.z += w[q] * f1.x; acc.w += w[q] * f1.y;
        }
    }
    for (; j < end; j++) {
        int sx = g_csr_src[j];
        float w = g_dinv[sx] * dv;
        uint2 u = ((const uint2*)(fin + (size_t)sx * D_FEAT))[lane];
        float2 f0 = __half22float2(*(__half2*)&u.x);
        float2 f1 = __half22float2(*(__half2*)&u.y);
        acc.x += w * f0.x; acc.y += w * f0.y;
        acc.z += w * f1.x; acc.w += w * f1.y;
    }
    ((float4*)(fout + (size_t)v * D_FEAT))[lane] = acc;
}

// ---------------- GEMM (layers 1-2): H = relu(bufA @ W + b) -> fp16 g_bufH ----------
__global__ void __launch_bounds__(256) k_gemm(const float* __restrict__ W,
                                              const float* __restrict__ bias, int M) {
    const float* __restrict__ A = (const float*)g_bufA;
    __shared__ float As[16][65];
    __shared__ float Bs[16][128];

    const int t  = threadIdx.x;
    const int tx = t & 15;
    const int ty = t >> 4;
    const int m0 = blockIdx.x * 64;

    unsigned long long acc2[4][4];
#pragma unroll
    for (int i = 0; i < 4; i++)
#pragma unroll
        for (int j = 0; j < 4; j++) acc2[i][j] = 0ull;

    for (int k0 = 0; k0 < 128; k0 += 16) {
        {
            int r  = t >> 2;
            int c  = (t & 3) * 4;
            int gm = m0 + r;
            float4 v = make_float4(0.f, 0.f, 0.f, 0.f);
            if (gm < M) v = *(const float4*)(A + (size_t)gm * 128 + k0 + c);
            As[c + 0][r] = v.x; As[c + 1][r] = v.y;
            As[c + 2][r] = v.z; As[c + 3][r] = v.w;
        }
#pragma unroll
        for (int i = 0; i < 2; i++) {
            int idx = t + i * 256;
            int rr  = idx >> 5;
            int cc  = (idx & 31) * 4;
            *(float4*)&Bs[rr][cc] = *(const float4*)(W + (size_t)(k0 + rr) * 128 + cc);
        }
        __syncthreads();
#pragma unroll
        for (int kk = 0; kk < 16; kk++) {
            unsigned long long ap[4], bv[4];
#pragma unroll
            for (int i = 0; i < 4; i++) {
                float a = As[kk][ty * 4 + i];
                ap[i] = pack2(a, a);
            }
#pragma unroll
            for (int j = 0; j < 4; j++)
                bv[j] = *(const unsigned long long*)&Bs[kk][tx * 8 + 2 * j];
#pragma unroll
            for (int i = 0; i < 4; i++)
#pragma unroll
                for (int j = 0; j < 4; j++) ffma2(acc2[i][j], ap[i], bv[j]);
        }
        __syncthreads();
    }

#pragma unroll
    for (int i = 0; i < 4; i++) {
        int gm = m0 + ty * 4 + i;
        if (gm >= M) continue;
        float o[8];
#pragma unroll
        for (int j = 0; j < 4; j++) {
            float lo, hi; unpack2(acc2[i][j], lo, hi);
            int col = tx * 8 + 2 * j;
            o[2 * j]     = fmaxf(lo + bias[col], 0.f);
            o[2 * j + 1] = fmaxf(hi + bias[col + 1], 0.f);
        }
        __half2 h0 = __floats2half2_rn(o[0], o[1]);
        __half2 h1 = __floats2half2_rn(o[2], o[3]);
        __half2 h2 = __floats2half2_rn(o[4], o[5]);
        __half2 h3 = __floats2half2_rn(o[6], o[7]);
        uint4 u;
        u.x = *(unsigned*)&h0; u.y = *(unsigned*)&h1;
        u.z = *(unsigned*)&h2; u.w = *(unsigned*)&h3;
        *(uint4*)(g_bufH + (size_t)gm * 128 + tx * 8) = u;
    }
}

// ---------------- layer-3 GEMM + fused head ----------------
// H = relu(bufA @ W3 + b3) staged in SMEM (k-major); out = H @ Wo + bo.
__global__ void __launch_bounds__(256) k_gemm_final(
    const float* __restrict__ W3, const float* __restrict__ b3,
    const float* __restrict__ Wo, const float* __restrict__ bo,
    float* __restrict__ outp, int M)
{
    const float* __restrict__ A = (const float*)g_bufA;
    __shared__ float As[16][65];
    __shared__ float Bs[16][128];
    __shared__ float Hs[128][65];   // k-major H tile

    const int t  = threadIdx.x;
    const int tx = t & 15;
    const int ty = t >> 4;
    const int m0 = blockIdx.x * 64;

    unsigned long long acc2[4][4];
#pragma unroll
    for (int i = 0; i < 4; i++)
#pragma unroll
        for (int j = 0; j < 4; j++) acc2[i][j] = 0ull;

    for (int k0 = 0; k0 < 128; k0 += 16) {
        {
            int r  = t >> 2;
            int c  = (t & 3) * 4;
            int gm = m0 + r;
            float4 v = make_float4(0.f, 0.f, 0.f, 0.f);
            if (gm < M) v = *(const float4*)(A + (size_t)gm * 128 + k0 + c);
            As[c + 0][r] = v.x; As[c + 1][r] = v.y;
            As[c + 2][r] = v.z; As[c + 3][r] = v.w;
        }
#pragma unroll
        for (int i = 0; i < 2; i++) {
            int idx = t + i * 256;
            int rr  = idx >> 5;
            int cc  = (idx & 31) * 4;
            *(float4*)&Bs[rr][cc] = *(const float4*)(W3 + (size_t)(k0 + rr) * 128 + cc);
        }
        __syncthreads();
#pragma unroll
        for (int kk = 0; kk < 16; kk++) {
            unsigned long long ap[4], bv[4];
#pragma unroll
            for (int i = 0; i < 4; i++) {
                float a = As[kk][ty * 4 + i];
                ap[i] = pack2(a, a);
            }
#pragma unroll
            for (int j = 0; j < 4; j++)
                bv[j] = *(const unsigned long long*)&Bs[kk][tx * 8 + 2 * j];
#pragma unroll
            for (int i = 0; i < 4; i++)
#pragma unroll
                for (int j = 0; j < 4; j++) ffma2(acc2[i][j], ap[i], bv[j]);
        }
        __syncthreads();
    }

    // stage relu(H) into Hs (k-major)
#pragma unroll
    for (int i = 0; i < 4; i++) {
        int mloc = ty * 4 + i;
#pragma unroll
        for (int j = 0; j < 4; j++) {
            float lo, hi; unpack2(acc2[i][j], lo, hi);
            int col = tx * 8 + 2 * j;
            Hs[col][mloc]     = fmaxf(lo + b3[col], 0.f);
            Hs[col + 1][mloc] = fmaxf(hi + b3[col + 1], 0.f);
        }
    }
    __syncthreads();

    // head: out[64,64] = H @ Wo(128x64) + bo
    unsigned long long acc3[4][2];
#pragma unroll
    for (int i = 0; i < 4; i++) { acc3[i][0] = 0ull; acc3[i][1] = 0ull; }

    for (int k0 = 0; k0 < 128; k0 += 16) {
        {
            int rr = t >> 4;
            int cc = (t & 15) * 4;
            *(float4*)&Bs[rr][cc] = *(const float4*)(Wo + (size_t)(k0 + rr) * 64 + cc);
        }
        __syncthreads();
#pragma unroll
        for (int kk = 0; kk < 16; kk++) {
            unsigned long long ap[4], bv[2];
#pragma unroll
            for (int i = 0; i < 4; i++) {
                float a = Hs[k0 + kk][ty * 4 + i];
                ap[i] = pack2(a, a);
            }
#pragma unroll
            for (int j = 0; j < 2; j++)
                bv[j] = *(const unsigned long long*)&Bs[kk][tx * 4 + 2 * j];
#pragma unroll
            for (int i = 0; i < 4; i++)
#pragma unroll
                for (int j = 0; j < 2; j++) ffma2(acc3[i][j], ap[i], bv[j]);
        }
        __syncthreads();
    }
#pragma unroll
    for (int i = 0; i < 4; i++) {
        int gm = m0 + ty * 4 + i;
        if (gm >= M) continue;
        float o0, o1, o2, o3;
        unpack2(acc3[i][0], o0, o1);
        unpack2(acc3[i][1], o2, o3);
        int col = tx * 4;
        o0 += bo[col];     o1 += bo[col + 1];
        o2 += bo[col + 2]; o3 += bo[col + 3];
        *(float4*)(outp + (size_t)gm * 64 + col) = make_float4(o0, o1, o2, o3);
    }
}

// ---------------- launch ----------------
extern "C" void kernel_launch(void* const* d_in, const int* in_sizes, int n_in,
                              void* d_out, int out_size) {
    const float* x  = (const float*)d_in[0];
    const void*  ei = d_in[1];
    const float* w1 = (const float*)d_in[2];
    const float* b1 = (const float*)d_in[3];
    const float* w2 = (const float*)d_in[4];
    const float* b2 = (const float*)d_in[5];
    const float* w3 = (const float*)d_in[6];
    const float* b3 = (const float*)d_in[7];
    const float* wo = (const float*)d_in[8];
    const float* bo = (const float*)d_in[9];
    float* out = (float*)d_out;

    const int TB = 256;
    k_init   <<<(N_NODES + TB - 1) / TB, TB>>>((const int*)ei);
    k_histcvt<<<HIST_BLOCKS + CVT_BLOCKS, TB>>>(ei, x);
    k_scan   <<<1, 1024>>>();
    k_scatter<<<(N_EDGES / 4 + TB - 1) / TB, TB>>>(ei);

    const int AGG_BLOCKS  = (N_NODES * 32 + TB - 1) / TB;
    const int GEMM_BLOCKS = (N_NODES + 63) / 64;

    // layer 1
    k_agg<<<AGG_BLOCKS, TB>>>();
    k_gemm<<<GEMM_BLOCKS, TB>>>(w1, b1, N_NODES);
    // layer 2
    k_agg<<<AGG_BLOCKS, TB>>>();
    k_gemm<<<GEMM_BLOCKS, TB>>>(w2, b2, N_NODES);
    // layer 3 + head
    k_agg<<<AGG_BLOCKS, TB>>>();
    k_gemm_final<<<GEMM_BLOCKS, TB>>>(w3, b3, wo, bo, out, N_NODES);
}

// round 10
// speedup vs baseline: 1.1102x; 1.1102x over previous
#include <cuda_runtime.h>
#include <cuda_fp16.h>

#define N_NODES 10000
#define N_EDGES 640000
#define D_FEAT  128

// ---------------- scratch (static device globals; no allocations) ----------------
__device__ __align__(256) float  g_dinv[N_NODES];
__device__ __align__(256) int    g_count[N_NODES];
__device__ __align__(256) int    g_cur[N_NODES];
__device__ __align__(256) int    g_off[N_NODES + 1];
__device__ __align__(256) int2   g_csr[N_EDGES];           // {src, float bits of weight}
__device__ __align__(256) float  g_bufA[N_NODES * D_FEAT]; // agg output (fp32, GEMM A)
__device__ __align__(256) __half g_bufH[N_NODES * D_FEAT]; // fp16 features (agg input)
__device__ int g_is64;

// ---------------- packed f32x2 helpers (sm_100a) ----------------
__device__ __forceinline__ unsigned long long pack2(float x, float y) {
    unsigned long long r;
    asm("mov.b64 %0, {%1, %2};" : "=l"(r) : "f"(x), "f"(y));
    return r;
}
__device__ __forceinline__ void unpack2(unsigned long long v, float& x, float& y) {
    asm("mov.b64 {%0, %1}, %2;" : "=f"(x), "=f"(y) : "l"(v));
}
__device__ __forceinline__ void ffma2(unsigned long long& c,
                                      unsigned long long a, unsigned long long b) {
    asm("fma.rn.f32x2 %0, %1, %2, %0;" : "+l"(c) : "l"(a), "l"(b));
}

// ---------------- structure kernels ----------------

// zero counters + dtype-detect (warp 0 of block 0).
__global__ void k_init(const int* __restrict__ ei32) {
    int t = threadIdx.x;
    int i = blockIdx.x * blockDim.x + t;
    if (i < N_NODES) { g_count[i] = 0; g_cur[i] = 0; }
    if (blockIdx.x == 0 && t < 32) {
        int any = 0;
#pragma unroll 8
        for (int k = 0; k < 32; k++) any |= ei32[2 * (t * 32 + k) + 1];
        int is64 = __any_sync(0xffffffffu, any != 0) ? 0 : 1;
        if (t == 0) g_is64 = is64;
    }
}

__device__ __forceinline__ void load4(const void* ei, int base4, int row, int* v) {
    if (g_is64) {
        const longlong2* p = (const longlong2*)ei + row * (N_EDGES / 2) + base4 * 2;
        longlong2 a = p[0], b = p[1];
        v[0] = (int)a.x; v[1] = (int)a.y; v[2] = (int)b.x; v[3] = (int)b.y;
    } else {
        int4 a = ((const int4*)ei)[row * (N_EDGES / 4) + base4];
        v[0] = a.x; v[1] = a.y; v[2] = a.z; v[3] = a.w;
    }
}

#define HIST_BLOCKS ((N_EDGES / 4 + 255) / 256)          // 625
#define CVT_BLOCKS  ((N_NODES * D_FEAT / 4 + 255) / 256) // 1250

// fused: histogram of dst row (4 edges/thread) + fp32->fp16 convert of x
__global__ void k_histcvt(const void* __restrict__ ei, const float* __restrict__ x) {
    if (blockIdx.x < HIST_BLOCKS) {
        int i = blockIdx.x * blockDim.x + threadIdx.x;
        if (i < N_EDGES / 4) {
            int d[4];
            load4(ei, i, 1, d);
#pragma unroll
            for (int q = 0; q < 4; q++)
                if ((unsigned)d[q] < N_NODES) atomicAdd(&g_count[d[q]], 1);
        }
    } else {
        int i = (blockIdx.x - HIST_BLOCKS) * blockDim.x + threadIdx.x;
        if (i < N_NODES * D_FEAT / 4) {
            float4 v = ((const float4*)x)[i];
            __half2 h0 = __floats2half2_rn(v.x, v.y);
            __half2 h1 = __floats2half2_rn(v.z, v.w);
            uint2 u;
            u.x = *(unsigned*)&h0;
            u.y = *(unsigned*)&h1;
            ((uint2*)g_bufH)[i] = u;
        }
    }
}

// single-block exclusive scan of g_count -> g_off, plus dinv
__global__ void k_scan() {
    __shared__ int part[1024];
    const int CH = 10;
    int t = threadIdx.x;
    int base = t * CH;
    int s = 0;
#pragma unroll
    for (int i = 0; i < CH; i++) {
        int idx = base + i;
        if (idx < N_NODES) s += g_count[idx];
    }
    part[t] = s;
    __syncthreads();
    for (int d = 1; d < 1024; d <<= 1) {
        int v = (t >= d) ? part[t - d] : 0;
        __syncthreads();
        part[t] += v;
        __syncthreads();
    }
    int run = (t == 0) ? 0 : part[t - 1];
#pragma unroll
    for (int i = 0; i < CH; i++) {
        int idx = base + i;
        if (idx < N_NODES) {
            int c = g_count[idx];
            g_off[idx] = run;
            run += c;
            g_dinv[idx] = rsqrtf((float)(c + 1));   // +1 self-loop
        } else if (idx == N_NODES) {
            g_off[N_NODES] = run;
        }
    }
}

// CSR fill ({src, weight}), 4 edges per thread
__global__ void k_scatter(const void* __restrict__ ei) {
    int i = blockIdx.x * blockDim.x + threadIdx.x;
    if (i < N_EDGES / 4) {
        int s[4], d[4];
        load4(ei, i, 0, s);
        load4(ei, i, 1, d);
#pragma unroll
        for (int q = 0; q < 4; q++) {
            if ((unsigned)d[q] < N_NODES) {
                int p = g_off[d[q]] + atomicAdd(&g_cur[d[q]], 1);
                bool sv = (unsigned)s[q] < N_NODES;
                float w = sv ? (g_dinv[s[q]] * g_dinv[d[q]]) : 0.0f;
                g_csr[p] = make_int2(sv ? s[q] : 0, __float_as_int(w));
            }
        }
    }
}

// ---------------- aggregation: one warp per destination node ----------------
// out[v] = dinv[v]^2 * in[v] + sum_e w_e * in[src_e]
// Broadcast int2 CSR loads (precomputed weights), 8-edge unroll. [R6-proven]
__global__ void __launch_bounds__(256) k_agg() {
    const __half* __restrict__ fin = g_bufH;
    float* __restrict__ fout = g_bufA;

    int v    = (blockIdx.x * blockDim.x + threadIdx.x) >> 5;
    int lane = threadIdx.x & 31;
    if (v >= N_NODES) return;

    float dv = g_dinv[v];
    float sl = dv * dv;

    uint2 ux = ((const uint2*)(fin + (size_t)v * D_FEAT))[lane];
    float2 x0 = __half22float2(*(__half2*)&ux.x);
    float2 x1 = __half22float2(*(__half2*)&ux.y);
    float4 acc = make_float4(x0.x * sl, x0.y * sl, x1.x * sl, x1.y * sl);

    int j   = g_off[v];
    int end = g_off[v + 1];
    for (; j + 8 <= end; j += 8) {
        int2 e[8];
        uint2 u[8];
#pragma unroll
        for (int q = 0; q < 8; q++) e[q] = g_csr[j + q];
#pragma unroll
        for (int q = 0; q < 8; q++)
            u[q] = ((const uint2*)(fin + (size_t)e[q].x * D_FEAT))[lane];
#pragma unroll
        for (int q = 0; q < 8; q++) {
            float w = __int_as_float(e[q].y);
            float2 f0 = __half22float2(*(__half2*)&u[q].x);
            float2 f1 = __half22float2(*(__half2*)&u[q].y);
            acc.x += w * f0.x; acc.y += w * f0.y;
            acc.z += w * f1.x; acc.w += w * f1.y;
        }
    }
    for (; j < end; j++) {
        int2 e = g_csr[j];
        float w = __int_as_float(e.y);
        uint2 u = ((const uint2*)(fin + (size_t)e.x * D_FEAT))[lane];
        float2 f0 = __half22float2(*(__half2*)&u.x);
        float2 f1 = __half22float2(*(__half2*)&u.y);
        acc.x += w * f0.x; acc.y += w * f0.y;
        acc.z += w * f1.x; acc.w += w * f1.y;
    }
    ((float4*)(fout + (size_t)v * D_FEAT))[lane] = acc;
}

// ---------------- GEMM (layers 1-2): H = relu(bufA @ W + b) -> fp16 g_bufH ----------
__global__ void __launch_bounds__(256) k_gemm(const float* __restrict__ W,
                                              const float* __restrict__ bias, int M) {
    const float* __restrict__ A = (const float*)g_bufA;
    __shared__ float As[16][65];
    __shared__ float Bs[16][128];

    const int t  = threadIdx.x;
    const int tx = t & 15;
    const int ty = t >> 4;
    const int m0 = blockIdx.x * 64;

    unsigned long long acc2[4][4];
#pragma unroll
    for (int i = 0; i < 4; i++)
#pragma unroll
        for (int j = 0; j < 4; j++) acc2[i][j] = 0ull;

    for (int k0 = 0; k0 < 128; k0 += 16) {
        {
            int r  = t >> 2;
            int c  = (t & 3) * 4;
            int gm = m0 + r;
            float4 v = make_float4(0.f, 0.f, 0.f, 0.f);
            if (gm < M) v = *(const float4*)(A + (size_t)gm * 128 + k0 + c);
            As[c + 0][r] = v.x; As[c + 1][r] = v.y;
            As[c + 2][r] = v.z; As[c + 3][r] = v.w;
        }
#pragma unroll
        for (int i = 0; i < 2; i++) {
            int idx = t + i * 256;
            int rr  = idx >> 5;
            int cc  = (idx & 31) * 4;
            *(float4*)&Bs[rr][cc] = *(const float4*)(W + (size_t)(k0 + rr) * 128 + cc);
        }
        __syncthreads();
#pragma unroll
        for (int kk = 0; kk < 16; kk++) {
            unsigned long long ap[4], bv[4];
#pragma unroll
            for (int i = 0; i < 4; i++) {
                float a = As[kk][ty * 4 + i];
                ap[i] = pack2(a, a);
            }
#pragma unroll
            for (int j = 0; j < 4; j++)
                bv[j] = *(const unsigned long long*)&Bs[kk][tx * 8 + 2 * j];
#pragma unroll
            for (int i = 0; i < 4; i++)
#pragma unroll
                for (int j = 0; j < 4; j++) ffma2(acc2[i][j], ap[i], bv[j]);
        }
        __syncthreads();
    }

#pragma unroll
    for (int i = 0; i < 4; i++) {
        int gm = m0 + ty * 4 + i;
        if (gm >= M) continue;
        float o[8];
#pragma unroll
        for (int j = 0; j < 4; j++) {
            float lo, hi; unpack2(acc2[i][j], lo, hi);
            int col = tx * 8 + 2 * j;
            o[2 * j]     = fmaxf(lo + bias[col], 0.f);
            o[2 * j + 1] = fmaxf(hi + bias[col + 1], 0.f);
        }
        __half2 h0 = __floats2half2_rn(o[0], o[1]);
        __half2 h1 = __floats2half2_rn(o[2], o[3]);
        __half2 h2 = __floats2half2_rn(o[4], o[5]);
        __half2 h3 = __floats2half2_rn(o[6], o[7]);
        uint4 u;
        u.x = *(unsigned*)&h0; u.y = *(unsigned*)&h1;
        u.z = *(unsigned*)&h2; u.w = *(unsigned*)&h3;
        *(uint4*)(g_bufH + (size_t)gm * 128 + tx * 8) = u;
    }
}

// ---------------- layer-3 GEMM + fused head ----------------
// H = relu(bufA @ W3 + b3) staged in SMEM (k-major); out = H @ Wo + bo.
__global__ void __launch_bounds__(256) k_gemm_final(
    const float* __restrict__ W3, const float* __restrict__ b3,
    const float* __restrict__ Wo, const float* __restrict__ bo,
    float* __restrict__ outp, int M)
{
    const float* __restrict__ A = (const float*)g_bufA;
    __shared__ float As[16][65];
    __shared__ float Bs[16][128];
    __shared__ float Hs[128][65];   // k-major H tile

    const int t  = threadIdx.x;
    const int tx = t & 15;
    const int ty = t >> 4;
    const int m0 = blockIdx.x * 64;

    unsigned long long acc2[4][4];
#pragma unroll
    for (int i = 0; i < 4; i++)
#pragma unroll
        for (int j = 0; j < 4; j++) acc2[i][j] = 0ull;

    for (int k0 = 0; k0 < 128; k0 += 16) {
        {
            int r  = t >> 2;
            int c  = (t & 3) * 4;
            int gm = m0 + r;
            float4 v = make_float4(0.f, 0.f, 0.f, 0.f);
            if (gm < M) v = *(const float4*)(A + (size_t)gm * 128 + k0 + c);
            As[c + 0][r] = v.x; As[c + 1][r] = v.y;
            As[c + 2][r] = v.z; As[c + 3][r] = v.w;
        }
#pragma unroll
        for (int i = 0; i < 2; i++) {
            int idx = t + i * 256;
            int rr  = idx >> 5;
            int cc  = (idx & 31) * 4;
            *(float4*)&Bs[rr][cc] = *(const float4*)(W3 + (size_t)(k0 + rr) * 128 + cc);
        }
        __syncthreads();
#pragma unroll
        for (int kk = 0; kk < 16; kk++) {
            unsigned long long ap[4], bv[4];
#pragma unroll
            for (int i = 0; i < 4; i++) {
                float a = As[kk][ty * 4 + i];
                ap[i] = pack2(a, a);
            }
#pragma unroll
            for (int j = 0; j < 4; j++)
                bv[j] = *(const unsigned long long*)&Bs[kk][tx * 8 + 2 * j];
#pragma unroll
            for (int i = 0; i < 4; i++)
#pragma unroll
                for (int j = 0; j < 4; j++) ffma2(acc2[i][j], ap[i], bv[j]);
        }
        __syncthreads();
    }

    // stage relu(H) into Hs (k-major)
#pragma unroll
    for (int i = 0; i < 4; i++) {
        int mloc = ty * 4 + i;
#pragma unroll
        for (int j = 0; j < 4; j++) {
            float lo, hi; unpack2(acc2[i][j], lo, hi);
            int col = tx * 8 + 2 * j;
            Hs[col][mloc]     = fmaxf(lo + b3[col], 0.f);
            Hs[col + 1][mloc] = fmaxf(hi + b3[col + 1], 0.f);
        }
    }
    __syncthreads();

    // head: out[64,64] = H @ Wo(128x64) + bo
    unsigned long long acc3[4][2];
#pragma unroll
    for (int i = 0; i < 4; i++) { acc3[i][0] = 0ull; acc3[i][1] = 0ull; }

    for (int k0 = 0; k0 < 128; k0 += 16) {
        {
            int rr = t >> 4;
            int cc = (t & 15) * 4;
            *(float4*)&Bs[rr][cc] = *(const float4*)(Wo + (size_t)(k0 + rr) * 64 + cc);
        }
        __syncthreads();
#pragma unroll
        for (int kk = 0; kk < 16; kk++) {
            unsigned long long ap[4], bv[2];
#pragma unroll
            for (int i = 0; i < 4; i++) {
                float a = Hs[k0 + kk][ty * 4 + i];
                ap[i] = pack2(a, a);
            }
#pragma unroll
            for (int j = 0; j < 2; j++)
                bv[j] = *(const unsigned long long*)&Bs[kk][tx * 4 + 2 * j];
#pragma unroll
            for (int i = 0; i < 4; i++)
#pragma unroll
                for (int j = 0; j < 2; j++) ffma2(acc3[i][j], ap[i], bv[j]);
        }
        __syncthreads();
    }
#pragma unroll
    for (int i = 0; i < 4; i++) {
        int gm = m0 + ty * 4 + i;
        if (gm >= M) continue;
        float o0, o1, o2, o3;
        unpack2(acc3[i][0], o0, o1);
        unpack2(acc3[i][1], o2, o3);
        int col = tx * 4;
        o0 += bo[col];     o1 += bo[col + 1];
        o2 += bo[col + 2]; o3 += bo[col + 3];
        *(float4*)(outp + (size_t)gm * 64 + col) = make_float4(o0, o1, o2, o3);
    }
}

// ---------------- launch ----------------
extern "C" void kernel_launch(void* const* d_in, const int* in_sizes, int n_in,
                              void* d_out, int out_size) {
    const float* x  = (const float*)d_in[0];
    const void*  ei = d_in[1];
    const float* w1 = (const float*)d_in[2];
    const float* b1 = (const float*)d_in[3];
    const float* w2 = (const float*)d_in[4];
    const float* b2 = (const float*)d_in[5];
    const float* w3 = (const float*)d_in[6];
    const float* b3 = (const float*)d_in[7];
    const float* wo = (const float*)d_in[8];
    const float* bo = (const float*)d_in[9];
    float* out = (float*)d_out;

    const int TB = 256;
    k_init   <<<(N_NODES + TB - 1) / TB, TB>>>((const int*)ei);
    k_histcvt<<<HIST_BLOCKS + CVT_BLOCKS, TB>>>(ei, x);
    k_scan   <<<1, 1024>>>();
    k_scatter<<<(N_EDGES / 4 + TB - 1) / TB, TB>>>(ei);

    const int AGG_BLOCKS  = (N_NODES * 32 + TB - 1) / TB;
    const int GEMM_BLOCKS = (N_NODES + 63) / 64;

    // layer 1
    k_agg<<<AGG_BLOCKS, TB>>>();
    k_gemm<<<GEMM_BLOCKS, TB>>>(w1, b1, N_NODES);
    // layer 2
    k_agg<<<AGG_BLOCKS, TB>>>();
    k_gemm<<<GEMM_BLOCKS, TB>>>(w2, b2, N_NODES);
    // layer 3 + head
    k_agg<<<AGG_BLOCKS, TB>>>();
    k_gemm_final<<<GEMM_BLOCKS, TB>>>(w3, b3, wo, bo, out, N_NODES);
}